// round 4
// baseline (speedup 1.0000x reference)
#include <cuda_runtime.h>
#include <cstdint>
#include <math_constants.h>

#define IN_DIM   128
#define HID      64
#define G_MAX    8192
#define CHUNK    128
#define THREADS  128
#define XS_STRIDE 129   // 128 + 1 pad -> conflict-free LDS in MLP and pool phases

// Shared memory layout (bytes)
#define XS_FLOATS   (CHUNK * XS_STRIDE)             // 16512 floats = 66048 B
#define WS_OFF      (XS_FLOATS * 4)                 // 66048 (16B aligned)
#define WS_U64      (IN_DIM * (HID / 2))            // 4096 u64 = 32768 B
#define B1_OFF      (WS_OFF + WS_U64 * 8)           // 98816
#define W2_OFF      (B1_OFF + HID * 4)              // 99072
#define ES_OFF      (W2_OFF + HID * 4)              // 99328
#define RED_OFF     (ES_OFF + CHUNK * 4)            // 99840
#define SMEM_TOTAL  (RED_OFF + 32 * 4)              // 99968 B  (< 113.5 KB -> 2 CTAs/SM)

__device__ int g_seg_start[G_MAX + 1];
__device__ int g_is_i64;

// ---------------------------------------------------------------------------
// Kernel 0: dtype detector for `batch`.
// We always view the buffer as int32 (safe for both int32 and int64 storage).
// int64 little-endian: odd int32 indices are high words -> all zero (values in
// [0, 8192)). int32: odd indices near N/2 hold sorted values ~G/2 != 0.
// ---------------------------------------------------------------------------
__global__ void detect_i64_kernel(const int* __restrict__ b32, int n)
{
    int i64 = 1;
    #pragma unroll 1
    for (int k = 0; k < 64; ++k) {
        int j = ((n / 2) + 2 * k) | 1;   // odd index, j < n for our sizes
        if (j < n && b32[j] != 0) { i64 = 0; break; }
    }
    g_is_i64 = i64;
}

// ---------------------------------------------------------------------------
// Kernel 1: segment offsets from sorted batch (int32 view, stride 1 or 2).
// seg_start[g] = first index i with batch[i] >= g;  seg_start[G] = N.
// ---------------------------------------------------------------------------
__global__ void seg_offsets_kernel(const int* __restrict__ b32, int n, int G)
{
    int i = blockIdx.x * blockDim.x + threadIdx.x;
    if (i > n) return;
    const int s = g_is_i64 ? 2 : 1;      // int64 -> read low word at 2*i
    int cur  = (i < n) ? b32[(size_t)i * s]       : G;
    int prev = (i > 0) ? b32[(size_t)(i - 1) * s] : -1;
    cur  = min(max(cur,  -1), G);        // clamp: garbage can never index OOB
    prev = min(max(prev, -1), G);
    for (int g = prev + 1; g <= cur; ++g)
        g_seg_start[g] = i;              // g in [0, G] subset of [0, G_MAX]
}

// packed f32x2 FMA (FFMA2) — only reachable via PTX, 2x tput vs scalar FFMA
__device__ __forceinline__ unsigned long long ffma2(unsigned long long a,
                                                    unsigned long long b,
                                                    unsigned long long c)
{
    unsigned long long d;
    asm("fma.rn.f32x2 %0, %1, %2, %3;" : "=l"(d) : "l"(a), "l"(b), "l"(c));
    return d;
}

__device__ __forceinline__ unsigned long long pack_dup(float x)
{
    unsigned long long r;
    uint32_t xu = __float_as_uint(x);
    asm("mov.b64 %0, {%1, %1};" : "=l"(r) : "r"(xu));
    return r;
}

__device__ __forceinline__ void unpack2(unsigned long long v, float& lo, float& hi)
{
    uint32_t l, h;
    asm("mov.b64 {%0, %1}, %2;" : "=r"(l), "=r"(h) : "l"(v));
    lo = __uint_as_float(l);
    hi = __uint_as_float(h);
}

// ---------------------------------------------------------------------------
// Kernel 2: fused gate-MLP + online segment softmax + weighted pooling.
// One CTA per graph; nodes processed in 128-node chunks staged in SMEM.
// x is read from DRAM exactly once.
// ---------------------------------------------------------------------------
__global__ __launch_bounds__(THREADS)
void attn_pool_kernel(const float* __restrict__ x,
                      const float* __restrict__ W1,
                      const float* __restrict__ b1,
                      const float* __restrict__ W2,
                      const float* __restrict__ b2,
                      float* __restrict__ out)
{
    extern __shared__ char smem[];
    float*              xs  = (float*)smem;                         // [CHUNK][129]
    unsigned long long* ws  = (unsigned long long*)(smem + WS_OFF); // W1 as f32 pairs
    float*              b1s = (float*)(smem + B1_OFF);
    float*              w2s = (float*)(smem + W2_OFF);
    float*              es  = (float*)(smem + ES_OFF);              // exp weights
    float*              red = (float*)(smem + RED_OFF);             // reduce scratch

    const int tid  = threadIdx.x;
    const int lane = tid & 31;
    const int wid  = tid >> 5;
    const int g    = blockIdx.x;

    const int start = g_seg_start[g];
    const int end   = g_seg_start[g + 1];

    // Stage weights: W1 row-major [128][64] -> float2 pairs, identical layout.
    {
        const unsigned long long* w1u = (const unsigned long long*)W1;
        for (int i = tid; i < WS_U64; i += THREADS) ws[i] = w1u[i];
        if (tid < HID) { b1s[tid] = b1[tid]; w2s[tid] = W2[tid]; }
    }
    const float b2v = b2[0];

    float m_run = -CUDART_INF_F;
    float s_run = 0.f;
    float acc   = 0.f;   // thread tid owns output dim tid

    for (int cs = start; cs < end; cs += CHUNK) {
        const int c = min(CHUNK, end - cs);
        __syncthreads();   // xs/es from previous chunk fully consumed

        // ---- load x chunk (coalesced float4 LDG, scalar STS into padded rows)
        {
            const float4* x4 = (const float4*)x;
            const int total = c * (IN_DIM / 4);
            for (int i = tid; i < total; i += THREADS) {
                const int row = i >> 5;      // node within chunk
                const int c4  = i & 31;      // float4 column
                float4 v = x4[(size_t)(cs + row) * (IN_DIM / 4) + c4];
                float* dst = xs + row * XS_STRIDE + c4 * 4;
                dst[0] = v.x; dst[1] = v.y; dst[2] = v.z; dst[3] = v.w;
            }
        }
        __syncthreads();

        // ---- gate MLP: one node per thread, FFMA2 packed accumulators
        float gate = -CUDART_INF_F;
        if (tid < c) {
            unsigned long long h[HID / 2];
            const unsigned long long zero2 = pack_dup(0.f);
            #pragma unroll
            for (int p = 0; p < HID / 2; ++p) h[p] = zero2;

            const float* xr = xs + tid * XS_STRIDE;   // bank (tid+k)%32 -> conflict-free
            #pragma unroll 2
            for (int k = 0; k < IN_DIM; ++k) {
                const unsigned long long x2 = pack_dup(xr[k]);
                // LDS.128: two f32-pairs per load, broadcast across the warp
                const ulonglong2* wr = (const ulonglong2*)(ws + k * (HID / 2));
                #pragma unroll
                for (int p = 0; p < HID / 4; ++p) {
                    ulonglong2 wv = wr[p];
                    h[2 * p]     = ffma2(x2, wv.x, h[2 * p]);
                    h[2 * p + 1] = ffma2(x2, wv.y, h[2 * p + 1]);
                }
            }
            float gacc = b2v;
            #pragma unroll
            for (int p = 0; p < HID / 2; ++p) {
                float lo, hi;
                unpack2(h[p], lo, hi);
                lo = fmaxf(lo + b1s[2 * p], 0.f);
                hi = fmaxf(hi + b1s[2 * p + 1], 0.f);
                gacc = fmaf(lo, w2s[2 * p], gacc);
                gacc = fmaf(hi, w2s[2 * p + 1], gacc);
            }
            gate = gacc;
        }

        // ---- chunk max (warp shuffle + smem)
        float v = gate;
        #pragma unroll
        for (int o = 16; o; o >>= 1) v = fmaxf(v, __shfl_xor_sync(0xffffffffu, v, o));
        if (lane == 0) red[wid] = v;
        __syncthreads();
        const float cmax  = fmaxf(fmaxf(red[0], red[1]), fmaxf(red[2], red[3]));
        const float m_new = fmaxf(m_run, cmax);
        const float resc  = expf(m_run - m_new);   // first chunk: exp(-inf) = 0

        const float e = (tid < c) ? expf(gate - m_new) : 0.f;
        __syncthreads();   // everyone done reading red (max) before reuse
        es[tid] = e;
        float sv = e;
        #pragma unroll
        for (int o = 16; o; o >>= 1) sv += __shfl_xor_sync(0xffffffffu, sv, o);
        if (lane == 0) red[wid] = sv;
        __syncthreads();
        const float csum = red[0] + red[1] + red[2] + red[3];

        s_run = s_run * resc + csum;
        m_run = m_new;

        // ---- weighted accumulate: thread d sums e[n]*xs[n][d]  (conflict-free)
        acc *= resc;
        #pragma unroll 4
        for (int n = 0; n < c; ++n)
            acc = fmaf(es[n], xs[n * XS_STRIDE + tid], acc);
    }

    out[(size_t)g * IN_DIM + tid] = (end > start) ? (acc / s_run) : 0.f;
}

// ---------------------------------------------------------------------------
extern "C" void kernel_launch(void* const* d_in, const int* in_sizes, int n_in,
                              void* d_out, int out_size)
{
    const float* x     = (const float*)d_in[0];
    const int*   b32   = (const int*)d_in[1];   // int32 view: safe for i32/i64
    const float* W1    = (const float*)d_in[2];
    const float* b1    = (const float*)d_in[3];
    const float* W2    = (const float*)d_in[4];
    const float* b2    = (const float*)d_in[5];
    float*       out   = (float*)d_out;

    const int N = in_sizes[0] / IN_DIM;
    int G = out_size / IN_DIM;
    if (G > G_MAX) G = G_MAX;

    detect_i64_kernel<<<1, 1>>>(b32, N);
    seg_offsets_kernel<<<(N + 1 + 255) / 256, 256>>>(b32, N, G);

    cudaFuncSetAttribute(attn_pool_kernel,
                         cudaFuncAttributeMaxDynamicSharedMemorySize, SMEM_TOTAL);
    attn_pool_kernel<<<G, THREADS, SMEM_TOTAL>>>(x, W1, b1, W2, b2, out);
}